// round 1
// baseline (speedup 1.0000x reference)
#include <cuda_runtime.h>
#include <cstdint>

// Inputs (metadata order):
//   d_in[0] user_emb   float32 [N_USERS * 64]
//   d_in[1] entity_emb float32 [N_ENTITIES * 64]
//   d_in[2] rows       int32   [NNZ]
//   d_in[3] cols       int32   [NNZ]
//   d_in[4] vals       float32 [NNZ]
// Output: entity_agg [N_ENTITIES*64] followed by user_agg [N_USERS*64], float32.

static constexpr int D = 64;
static constexpr int D4 = D / 4;          // 16 float4 per row
static constexpr int THREADS_PER_EDGE = 16;

__global__ void zero_kernel(float4* out, long long n4) {
    long long i = (long long)blockIdx.x * blockDim.x + threadIdx.x;
    if (i < n4) out[i] = make_float4(0.f, 0.f, 0.f, 0.f);
}

__device__ __forceinline__ void red_add_v4(float* ptr, float4 v) {
    asm volatile("red.global.add.v4.f32 [%0], {%1, %2, %3, %4};"
                 :: "l"(ptr), "f"(v.x), "f"(v.y), "f"(v.z), "f"(v.w)
                 : "memory");
}

__global__ void __launch_bounds__(256)
agg_kernel(const float4* __restrict__ user_emb,
           const float4* __restrict__ entity_emb,
           const int* __restrict__ rows,
           const int* __restrict__ cols,
           const float* __restrict__ vals,
           float* __restrict__ entity_agg,
           float* __restrict__ user_agg,
           int nnz) {
    long long gid = (long long)blockIdx.x * blockDim.x + threadIdx.x;
    long long e = gid >> 4;                 // edge index
    int c = (int)(gid & 15);                // float4 chunk within the 64-dim row
    if (e >= nnz) return;

    int row = rows[e];
    int col = cols[e];
    float v = vals[e];

    // entity_agg[col] += v * user_emb[row]
    float4 u = user_emb[(long long)row * D4 + c];
    u.x *= v; u.y *= v; u.z *= v; u.w *= v;
    red_add_v4(entity_agg + (long long)col * D + c * 4, u);

    // user_agg[row] += v * entity_emb[col]
    float4 t = entity_emb[(long long)col * D4 + c];
    t.x *= v; t.y *= v; t.z *= v; t.w *= v;
    red_add_v4(user_agg + (long long)row * D + c * 4, t);
}

extern "C" void kernel_launch(void* const* d_in, const int* in_sizes, int n_in,
                              void* d_out, int out_size) {
    const float4* user_emb   = (const float4*)d_in[0];
    const float4* entity_emb = (const float4*)d_in[1];
    const int*    rows       = (const int*)d_in[2];
    const int*    cols       = (const int*)d_in[3];
    const float*  vals       = (const float*)d_in[4];

    int nnz        = in_sizes[2];
    int n_entities = in_sizes[1] / D;

    float* out        = (float*)d_out;
    float* entity_agg = out;                                   // [n_entities * D]
    float* user_agg   = out + (long long)n_entities * D;       // [n_users * D]

    // Zero-initialize the output (poisoned by harness).
    long long n4 = (long long)out_size / 4;
    int zthreads = 256;
    long long zblocks = (n4 + zthreads - 1) / zthreads;
    zero_kernel<<<(unsigned)zblocks, zthreads>>>((float4*)d_out, n4);

    // One 16-thread group per edge.
    long long total = (long long)nnz * THREADS_PER_EDGE;
    int threads = 256;
    long long blocks = (total + threads - 1) / threads;
    agg_kernel<<<(unsigned)blocks, threads>>>(user_emb, entity_emb, rows, cols,
                                              vals, entity_agg, user_agg, nnz);
}

// round 3
// speedup vs baseline: 1.1196x; 1.1196x over previous
#include <cuda_runtime.h>
#include <cstdint>

// LightAggregator: bidirectional COO scatter-add, reformulated as CSR-gather.
//   entity_agg[c] = sum over edges (r,c,v): v * user_emb[r]
//   user_agg[r]   = sum over edges (r,c,v): v * entity_emb[c]
// Build both CSRs per call (counts -> scan -> scatter), then one fused gather
// kernel: half-warp per segment, accumulate in registers, single store.
//
// Inputs (metadata order):
//   d_in[0] user_emb   float32 [N_USERS * 64]
//   d_in[1] entity_emb float32 [N_ENTITIES * 64]
//   d_in[2] rows       int32   [NNZ]
//   d_in[3] cols       int32   [NNZ]
//   d_in[4] vals       float32 [NNZ]
// Output: entity_agg [N_ENTITIES*64] ++ user_agg [N_USERS*64], float32.

static constexpr int D  = 64;
static constexpr int D4 = D / 4;       // float4 per row

static constexpr int MAX_SEG = 150016;    // >= n_entities + n_users
static constexpr int MAX_EDGE2 = 4000000; // 2 * NNZ entries

// Static device scratch (no allocation allowed).
__device__ int    g_count[MAX_SEG];
__device__ int    g_start[MAX_SEG + 1];
__device__ int    g_cursor[MAX_SEG];
__device__ int    g_bsums[256];
__device__ float2 g_edges[MAX_EDGE2];    // (neighbor_idx as int bits, val)

static constexpr int SCAN_BLK = 1024;

// ---------- build ----------

__global__ void zero_counts_kernel(int n_seg) {
    int i = blockIdx.x * blockDim.x + threadIdx.x;
    if (i < n_seg) g_count[i] = 0;
}

__global__ void hist_kernel(const int* __restrict__ rows,
                            const int* __restrict__ cols,
                            int nnz, int ne) {
    int e = blockIdx.x * blockDim.x + threadIdx.x;
    if (e >= nnz) return;
    atomicAdd(&g_count[cols[e]], 1);          // entity segment
    atomicAdd(&g_count[ne + rows[e]], 1);     // user segment
}

// Per-block exclusive scan; block totals to g_bsums.
__global__ void scan_a_kernel(int n_seg) {
    __shared__ int s[SCAN_BLK];
    int tid = threadIdx.x;
    int gi  = blockIdx.x * SCAN_BLK + tid;
    int v   = (gi < n_seg) ? g_count[gi] : 0;
    s[tid] = v;
    __syncthreads();
    for (int off = 1; off < SCAN_BLK; off <<= 1) {
        int t = (tid >= off) ? s[tid - off] : 0;
        __syncthreads();
        s[tid] += t;
        __syncthreads();
    }
    if (gi < n_seg) g_start[gi] = s[tid] - v;     // exclusive within block
    if (tid == SCAN_BLK - 1) g_bsums[blockIdx.x] = s[tid];
}

// Single block: exclusive scan of block sums.
__global__ void scan_b_kernel(int nblocks) {
    __shared__ int s[256];
    int tid = threadIdx.x;
    int v = (tid < nblocks) ? g_bsums[tid] : 0;
    s[tid] = v;
    __syncthreads();
    for (int off = 1; off < 256; off <<= 1) {
        int t = (tid >= off) ? s[tid - off] : 0;
        __syncthreads();
        s[tid] += t;
        __syncthreads();
    }
    if (tid < nblocks) g_bsums[tid] = s[tid] - v; // exclusive
}

__global__ void scan_c_kernel(int n_seg, int total) {
    int i = blockIdx.x * blockDim.x + threadIdx.x;
    if (i < n_seg) {
        int v = g_start[i] + g_bsums[i / SCAN_BLK];
        g_start[i]  = v;
        g_cursor[i] = v;
    }
    if (i == 0) g_start[n_seg] = total;
}

__global__ void scatter_kernel(const int* __restrict__ rows,
                               const int* __restrict__ cols,
                               const float* __restrict__ vals,
                               int nnz, int ne) {
    int e = blockIdx.x * blockDim.x + threadIdx.x;
    if (e >= nnz) return;
    int r = rows[e];
    int c = cols[e];
    float v = vals[e];
    int p0 = atomicAdd(&g_cursor[c], 1);
    g_edges[p0] = make_float2(__int_as_float(r), v);
    int p1 = atomicAdd(&g_cursor[ne + r], 1);
    g_edges[p1] = make_float2(__int_as_float(c), v);
}

// ---------- gather ----------
// Half-warp (16 lanes) per segment; lane owns one float4 of the 64-dim row.
// 2-way unrolled so two independent embedding gathers are in flight.

__global__ void __launch_bounds__(256)
gather_kernel(const float4* __restrict__ user_emb,
              const float4* __restrict__ entity_emb,
              float4* __restrict__ entity_agg,
              float4* __restrict__ user_agg,
              int n_seg, int ne) {
    int gid  = blockIdx.x * blockDim.x + threadIdx.x;
    int s    = gid >> 4;
    int lane = gid & 15;
    if (s >= n_seg) return;

    int beg = g_start[s];
    int end = g_start[s + 1];

    const float4* __restrict__ src;
    float4* dst;
    if (s < ne) {
        src = user_emb;
        dst = entity_agg + (long long)s * D4;
    } else {
        src = entity_emb;
        dst = user_agg + (long long)(s - ne) * D4;
    }

    float4 acc0 = make_float4(0.f, 0.f, 0.f, 0.f);
    float4 acc1 = make_float4(0.f, 0.f, 0.f, 0.f);
    int i = beg;
    for (; i + 1 < end; i += 2) {
        float2 e0 = g_edges[i];
        float2 e1 = g_edges[i + 1];
        int   i0 = __float_as_int(e0.x);
        int   i1 = __float_as_int(e1.x);
        float v0 = e0.y;
        float v1 = e1.y;
        float4 x0 = src[(long long)i0 * D4 + lane];
        float4 x1 = src[(long long)i1 * D4 + lane];
        acc0.x = fmaf(v0, x0.x, acc0.x);
        acc0.y = fmaf(v0, x0.y, acc0.y);
        acc0.z = fmaf(v0, x0.z, acc0.z);
        acc0.w = fmaf(v0, x0.w, acc0.w);
        acc1.x = fmaf(v1, x1.x, acc1.x);
        acc1.y = fmaf(v1, x1.y, acc1.y);
        acc1.z = fmaf(v1, x1.z, acc1.z);
        acc1.w = fmaf(v1, x1.w, acc1.w);
    }
    if (i < end) {
        float2 e0 = g_edges[i];
        int   i0 = __float_as_int(e0.x);
        float v0 = e0.y;
        float4 x0 = src[(long long)i0 * D4 + lane];
        acc0.x = fmaf(v0, x0.x, acc0.x);
        acc0.y = fmaf(v0, x0.y, acc0.y);
        acc0.z = fmaf(v0, x0.z, acc0.z);
        acc0.w = fmaf(v0, x0.w, acc0.w);
    }
    acc0.x += acc1.x; acc0.y += acc1.y; acc0.z += acc1.z; acc0.w += acc1.w;
    dst[lane] = acc0;
}

// ---------- launch ----------

extern "C" void kernel_launch(void* const* d_in, const int* in_sizes, int n_in,
                              void* d_out, int out_size) {
    const float4* user_emb   = (const float4*)d_in[0];
    const float4* entity_emb = (const float4*)d_in[1];
    const int*    rows       = (const int*)d_in[2];
    const int*    cols       = (const int*)d_in[3];
    const float*  vals       = (const float*)d_in[4];

    int nu  = in_sizes[0] / D;
    int ne  = in_sizes[1] / D;
    int nnz = in_sizes[2];
    int n_seg = ne + nu;

    float* out = (float*)d_out;
    float4* entity_agg = (float4*)out;
    float4* user_agg   = (float4*)(out + (long long)ne * D);

    int T = 256;
    int seg_blocks  = (n_seg + T - 1) / T;
    int edge_blocks = (nnz + T - 1) / T;
    int scan_blocks = (n_seg + SCAN_BLK - 1) / SCAN_BLK;

    zero_counts_kernel<<<seg_blocks, T>>>(n_seg);
    hist_kernel<<<edge_blocks, T>>>(rows, cols, nnz, ne);
    scan_a_kernel<<<scan_blocks, SCAN_BLK>>>(n_seg);
    scan_b_kernel<<<1, 256>>>(scan_blocks);
    scan_c_kernel<<<seg_blocks, T>>>(n_seg, 2 * nnz);
    scatter_kernel<<<edge_blocks, T>>>(rows, cols, vals, nnz, ne);

    long long total_threads = (long long)n_seg * 16;
    int gather_blocks = (int)((total_threads + T - 1) / T);
    gather_kernel<<<gather_blocks, T>>>(user_emb, entity_emb,
                                        entity_agg, user_agg, n_seg, ne);
}

// round 4
// speedup vs baseline: 1.1479x; 1.0253x over previous
#include <cuda_runtime.h>
#include <cstdint>

// LightAggregator: bidirectional COO scatter-add as CSR-gather.
//   entity_agg[c] = sum over edges (r,c,v): v * user_emb[r]
//   user_agg[r]   = sum over edges (r,c,v): v * entity_emb[c]
// Build: counts -> single-pass block scan with atomic slice reservation
// (segment slices are contiguous but globally unordered — CSR doesn't care)
// -> scatter (idx,val) pairs -> fused register-accumulating gather.
//
// Inputs: d_in[0] user_emb f32[NU*64], d_in[1] entity_emb f32[NE*64],
//         d_in[2] rows i32[NNZ], d_in[3] cols i32[NNZ], d_in[4] vals f32[NNZ]
// Output: entity_agg [NE*64] ++ user_agg [NU*64], f32.

static constexpr int D  = 64;
static constexpr int D4 = D / 4;

static constexpr int MAX_SEG   = 150016;   // >= n_entities + n_users
static constexpr int MAX_EDGE2 = 4000000;  // 2 * NNZ

__device__ int    g_count[MAX_SEG];
__device__ int    g_start[MAX_SEG];
__device__ int    g_cursor[MAX_SEG];
__device__ int    g_total;
__device__ float2 g_edges[MAX_EDGE2];      // (neighbor_idx bits, val)

static constexpr int SCAN_BLK = 1024;

// ---------- build ----------

__global__ void zero_counts_kernel(int n_seg) {
    int i = blockIdx.x * blockDim.x + threadIdx.x;
    if (i < n_seg) g_count[i] = 0;
    if (i == 0) g_total = 0;
}

__global__ void hist_kernel(const int* __restrict__ rows,
                            const int* __restrict__ cols,
                            int nnz, int ne) {
    int e = blockIdx.x * blockDim.x + threadIdx.x;
    if (e >= nnz) return;
    atomicAdd(&g_count[cols[e]], 1);
    atomicAdd(&g_count[ne + rows[e]], 1);
}

// Single-pass: block-local exclusive scan, then one atomicAdd reserves the
// block's contiguous slice of the edge array. Slice order across blocks is
// arbitrary (run-to-run deterministic is not required for correctness: the
// gather reads via g_start/g_count, and addition is reordered anyway —
// rel_err tolerance covers fp non-determinism; values per segment are fixed).
__global__ void scan_alloc_kernel(int n_seg) {
    __shared__ int s[SCAN_BLK];
    __shared__ int base;
    int tid = threadIdx.x;
    int gi  = blockIdx.x * SCAN_BLK + tid;
    int v   = (gi < n_seg) ? g_count[gi] : 0;
    s[tid] = v;
    __syncthreads();
    for (int off = 1; off < SCAN_BLK; off <<= 1) {
        int t = (tid >= off) ? s[tid - off] : 0;
        __syncthreads();
        s[tid] += t;
        __syncthreads();
    }
    if (tid == SCAN_BLK - 1) base = atomicAdd(&g_total, s[tid]);
    __syncthreads();
    if (gi < n_seg) {
        int st = base + s[tid] - v;   // exclusive within block + block base
        g_start[gi]  = st;
        g_cursor[gi] = st;
    }
}

__global__ void scatter_kernel(const int* __restrict__ rows,
                               const int* __restrict__ cols,
                               const float* __restrict__ vals,
                               int nnz, int ne) {
    int e = blockIdx.x * blockDim.x + threadIdx.x;
    if (e >= nnz) return;
    int r = rows[e];
    int c = cols[e];
    float v = vals[e];
    int p0 = atomicAdd(&g_cursor[c], 1);
    g_edges[p0] = make_float2(__int_as_float(r), v);
    int p1 = atomicAdd(&g_cursor[ne + r], 1);
    g_edges[p1] = make_float2(__int_as_float(c), v);
}

// ---------- gather ----------
// Half-warp per segment, lane owns one float4 of the row. 4-wide unroll keeps
// 4 independent embedding gathers in flight to hide L2 latency.

__global__ void __launch_bounds__(256)
gather_kernel(const float4* __restrict__ user_emb,
              const float4* __restrict__ entity_emb,
              float4* __restrict__ entity_agg,
              float4* __restrict__ user_agg,
              int n_seg, int ne) {
    int gid  = blockIdx.x * blockDim.x + threadIdx.x;
    int s    = gid >> 4;
    int lane = gid & 15;
    if (s >= n_seg) return;

    int beg = g_start[s];
    int end = beg + g_count[s];

    const float4* __restrict__ src;
    float4* dst;
    if (s < ne) {
        src = user_emb;
        dst = entity_agg + (long long)s * D4;
    } else {
        src = entity_emb;
        dst = user_agg + (long long)(s - ne) * D4;
    }

    float4 acc0 = make_float4(0.f, 0.f, 0.f, 0.f);
    float4 acc1 = make_float4(0.f, 0.f, 0.f, 0.f);
    int i = beg;
    for (; i + 3 < end; i += 4) {
        float2 e0 = g_edges[i];
        float2 e1 = g_edges[i + 1];
        float2 e2 = g_edges[i + 2];
        float2 e3 = g_edges[i + 3];
        float4 x0 = src[(long long)__float_as_int(e0.x) * D4 + lane];
        float4 x1 = src[(long long)__float_as_int(e1.x) * D4 + lane];
        float4 x2 = src[(long long)__float_as_int(e2.x) * D4 + lane];
        float4 x3 = src[(long long)__float_as_int(e3.x) * D4 + lane];
        acc0.x = fmaf(e0.y, x0.x, acc0.x);
        acc0.y = fmaf(e0.y, x0.y, acc0.y);
        acc0.z = fmaf(e0.y, x0.z, acc0.z);
        acc0.w = fmaf(e0.y, x0.w, acc0.w);
        acc1.x = fmaf(e1.y, x1.x, acc1.x);
        acc1.y = fmaf(e1.y, x1.y, acc1.y);
        acc1.z = fmaf(e1.y, x1.z, acc1.z);
        acc1.w = fmaf(e1.y, x1.w, acc1.w);
        acc0.x = fmaf(e2.y, x2.x, acc0.x);
        acc0.y = fmaf(e2.y, x2.y, acc0.y);
        acc0.z = fmaf(e2.y, x2.z, acc0.z);
        acc0.w = fmaf(e2.y, x2.w, acc0.w);
        acc1.x = fmaf(e3.y, x3.x, acc1.x);
        acc1.y = fmaf(e3.y, x3.y, acc1.y);
        acc1.z = fmaf(e3.y, x3.z, acc1.z);
        acc1.w = fmaf(e3.y, x3.w, acc1.w);
    }
    for (; i < end; i++) {
        float2 e0 = g_edges[i];
        float4 x0 = src[(long long)__float_as_int(e0.x) * D4 + lane];
        acc0.x = fmaf(e0.y, x0.x, acc0.x);
        acc0.y = fmaf(e0.y, x0.y, acc0.y);
        acc0.z = fmaf(e0.y, x0.z, acc0.z);
        acc0.w = fmaf(e0.y, x0.w, acc0.w);
    }
    acc0.x += acc1.x; acc0.y += acc1.y; acc0.z += acc1.z; acc0.w += acc1.w;
    dst[lane] = acc0;
}

// ---------- launch ----------

extern "C" void kernel_launch(void* const* d_in, const int* in_sizes, int n_in,
                              void* d_out, int out_size) {
    const float4* user_emb   = (const float4*)d_in[0];
    const float4* entity_emb = (const float4*)d_in[1];
    const int*    rows       = (const int*)d_in[2];
    const int*    cols       = (const int*)d_in[3];
    const float*  vals       = (const float*)d_in[4];

    int ne  = in_sizes[1] / D;
    int nnz = in_sizes[2];
    int nu  = in_sizes[0] / D;
    int n_seg = ne + nu;

    float* out = (float*)d_out;
    float4* entity_agg = (float4*)out;
    float4* user_agg   = (float4*)(out + (long long)ne * D);

    int T = 256;
    int seg_blocks  = (n_seg + T - 1) / T;
    int edge_blocks = (nnz + T - 1) / T;
    int scan_blocks = (n_seg + SCAN_BLK - 1) / SCAN_BLK;

    zero_counts_kernel<<<seg_blocks, T>>>(n_seg);
    hist_kernel<<<edge_blocks, T>>>(rows, cols, nnz, ne);
    scan_alloc_kernel<<<scan_blocks, SCAN_BLK>>>(n_seg);
    scatter_kernel<<<edge_blocks, T>>>(rows, cols, vals, nnz, ne);

    long long total_threads = (long long)n_seg * 16;
    int gather_blocks = (int)((total_threads + T - 1) / T);
    gather_kernel<<<gather_blocks, T>>>(user_emb, entity_emb,
                                        entity_agg, user_agg, n_seg, ne);
}